// round 17
// baseline (speedup 1.0000x reference)
#include <cuda_runtime.h>
#include <cstdint>

#define NEG_INF_F (-1e10f)
// Shapes: B=32, M=64, C=36, INPUT=1024, HID=512, NCLASS=1000 (padded to 1024)

// ---------------- scratch (device globals; no allocation allowed) ----------
__device__ float    g_men_h[2048 * 512];
__device__ float    g_men  [2048 * 512];
__device__ float    g_vis_h[1152 * 512];
__device__ float    g_vis  [1152 * 512];
__device__ float    g_cl_pad[1152 * 1024];
__device__ unsigned g_mw1t[1024 * 512];
__device__ unsigned g_mw2t[ 512 * 512];
__device__ unsigned g_vw1t[1024 * 512];
__device__ unsigned g_vw2t[ 512 * 512];
// aw1 packed in mma-fragment order: 512 chunks x 576 words (incl. skew holes)
__device__ __align__(16) unsigned g_aw1p[512 * 576];

// ---------------- PTX helpers ---------------------------------------------
__device__ __forceinline__ unsigned f2tf32(float x) {
    unsigned u;
    asm("cvt.rna.tf32.f32 %0, %1;" : "=r"(u) : "f"(x));
    return u;
}

__device__ __forceinline__ void mma_tf32(float c[4],
                                         unsigned a0, unsigned a1, unsigned a2, unsigned a3,
                                         unsigned b0, unsigned b1) {
    asm volatile(
        "mma.sync.aligned.m16n8k8.row.col.f32.tf32.tf32.f32 "
        "{%0,%1,%2,%3}, {%4,%5,%6,%7}, {%8,%9}, {%0,%1,%2,%3};\n"
        : "+f"(c[0]), "+f"(c[1]), "+f"(c[2]), "+f"(c[3])
        : "r"(a0), "r"(a1), "r"(a2), "r"(a3), "r"(b0), "r"(b1));
}

__device__ __forceinline__ void cp16(void* smem, const void* gmem) {
    unsigned s = (unsigned)__cvta_generic_to_shared(smem);
    asm volatile("cp.async.cg.shared.global [%0], [%1], 16;\n" :: "r"(s), "l"(gmem));
}
#define CP_COMMIT() asm volatile("cp.async.commit_group;\n" ::: "memory")
#define CP_WAIT0()  asm volatile("cp.async.wait_group 0;\n" ::: "memory")
#define CP_WAIT1()  asm volatile("cp.async.wait_group 1;\n" ::: "memory")

// ---------------- merged prep kernel ---------------------------------------
__global__ __launch_bounds__(256)
void prep_all(const float* __restrict__ cl,  float* __restrict__ clp,
              const float* __restrict__ mw1, unsigned* __restrict__ mw1t,
              const float* __restrict__ mw2, unsigned* __restrict__ mw2t,
              const float* __restrict__ vw1, unsigned* __restrict__ vw1t,
              const float* __restrict__ vw2, unsigned* __restrict__ vw2t,
              const float* __restrict__ aw1, unsigned* __restrict__ awp)
{
    const int b = blockIdx.x, t = threadIdx.x;
    if (b < 1152) {
        for (int c = t; c < 1024; c += 256)
            clp[b * 1024 + c] = (c < 1000) ? cl[b * 1000 + c] : 0.f;
    } else if (b < 2176) {
        int r = b - 1152;
        for (int c = t; c < 512; c += 256) mw1t[r * 512 + c] = f2tf32(mw1[r * 512 + c]);
    } else if (b < 2688) {
        int r = b - 2176;
        for (int c = t; c < 512; c += 256) mw2t[r * 512 + c] = f2tf32(mw2[r * 512 + c]);
    } else if (b < 3712) {
        int r = b - 2688;
        for (int c = t; c < 512; c += 256)
            vw1t[r * 512 + c] = (r < 1000) ? f2tf32(vw1[r * 512 + c]) : 0u;
    } else if (b < 4224) {
        int r = b - 3712;
        for (int c = t; c < 512; c += 256) vw2t[r * 512 + c] = f2tf32(vw2[r * 512 + c]);
    } else {
        // chunk = ((ni*16 + ksi)*4 + kc)*2 + h covers 8k x 64n.
        // Value (l, v): k = ksi*32+kc*8+(l&3)+4*(v&1), n = ni*128+h*64+(v>>1)*8+(l>>2).
        // In-chunk word offset = l*16 + (l>>1)*4 + v  (skew -> conflict-free LDS.128)
        int chunk = b - 4224;
        int h   = chunk & 1;
        int kc  = (chunk >> 1) & 3;
        int ksi = (chunk >> 3) & 15;
        int ni  = chunk >> 7;
#pragma unroll
        for (int p = 0; p < 2; p++) {
            int idx = t + p * 256;
            int l = idx >> 4, v = idx & 15;
            int k = ksi * 32 + kc * 8 + (l & 3) + 4 * (v & 1);
            int n = ni * 128 + h * 64 + (v >> 1) * 8 + (l >> 2);
            awp[chunk * 576 + l * 16 + (l >> 1) * 4 + v] = f2tf32(aw1[k * 512 + n]);
        }
    }
}

// ---------------- merged MLP GEMM (two row segments, one launch) -----------
template <bool RELU>
__global__ __launch_bounds__(256)
void gemm_mma2(const float* __restrict__ A0, const unsigned* __restrict__ W0,
               const float* __restrict__ b0p, float* __restrict__ C0,
               const float* __restrict__ A1, const unsigned* __restrict__ W1,
               const float* __restrict__ b1p, float* __restrict__ C1,
               int K, int y_split)
{
    __shared__ __align__(16) float    A_s[2][64][36];
    __shared__ __align__(16) unsigned B_s[2][32][72];

    const int tid = threadIdx.x;
    const int lane = tid & 31, wid = tid >> 5;
    const int wr = wid >> 1, wcl = wid & 1;

    const bool seg1 = (int)blockIdx.y >= y_split;
    const float*    A    = seg1 ? A1 : A0;
    const unsigned* W    = seg1 ? W1 : W0;
    const float*    bias = seg1 ? b1p : b0p;
    float*          C    = seg1 ? C1 : C0;
    const int row0 = (seg1 ? (blockIdx.y - y_split) : blockIdx.y) * 64;
    const int n0   = blockIdx.x * 64;

    float acc[4][4];
#pragma unroll
    for (int t = 0; t < 4; t++)
#pragma unroll
        for (int j = 0; j < 4; j++) acc[t][j] = 0.f;

    const int S = K >> 5;
    auto issue = [&](int s) {
        int buf = s & 1, k0 = s << 5;
#pragma unroll
        for (int p = 0; p < 2; p++) {
            int id = tid + p * 256;
            int r = id >> 3, k4 = id & 7;
            cp16(&A_s[buf][r][k4 * 4], A + (size_t)(row0 + r) * K + k0 + k4 * 4);
        }
#pragma unroll
        for (int p = 0; p < 2; p++) {
            int id = tid + p * 256;
            int kk = id >> 4, n4 = id & 15;
            cp16(&B_s[buf][kk][n4 * 4], W + (size_t)(k0 + kk) * 512 + n0 + n4 * 4);
        }
    };

    issue(0);
    CP_COMMIT();

    for (int s = 0; s < S; s++) {
        if (s + 1 < S) { issue(s + 1); CP_COMMIT(); CP_WAIT1(); }
        else           { CP_WAIT0(); }
        __syncthreads();
        const int buf = s & 1;
#pragma unroll
        for (int kc = 0; kc < 4; kc++) {
            const int k0 = kc * 8;
            const int ar = wr * 16 + (lane >> 2);
            const int ak = k0 + (lane & 3);
            unsigned a0 = f2tf32(A_s[buf][ar][ak]);
            unsigned a1 = f2tf32(A_s[buf][ar + 8][ak]);
            unsigned a2 = f2tf32(A_s[buf][ar][ak + 4]);
            unsigned a3 = f2tf32(A_s[buf][ar + 8][ak + 4]);
            const int bn = wcl * 32 + (lane >> 2);
#pragma unroll
            for (int t = 0; t < 4; t++) {
                unsigned b0 = B_s[buf][k0 + (lane & 3)][bn + t * 8];
                unsigned b1 = B_s[buf][k0 + (lane & 3) + 4][bn + t * 8];
                mma_tf32(acc[t], a0, a1, a2, a3, b0, b1);
            }
        }
        __syncthreads();
    }

    const int r = row0 + wr * 16 + (lane >> 2);
#pragma unroll
    for (int t = 0; t < 4; t++) {
        int n = n0 + wcl * 32 + t * 8 + 2 * (lane & 3);
        float b0v = __ldg(&bias[n]), b1v = __ldg(&bias[n + 1]);
        float v00 = acc[t][0] + b0v, v01 = acc[t][1] + b1v;
        float v10 = acc[t][2] + b0v, v11 = acc[t][3] + b1v;
        if (RELU) {
            v00 = fmaxf(v00, 0.f); v01 = fmaxf(v01, 0.f);
            v10 = fmaxf(v10, 0.f); v11 = fmaxf(v11, 0.f);
        }
        C[(size_t)r * 512 + n]           = v00;
        C[(size_t)r * 512 + n + 1]       = v01;
        C[(size_t)(r + 8) * 512 + n]     = v10;
        C[(size_t)(r + 8) * 512 + n + 1] = v11;
    }
}

// ---------------- fused attention: warp tile 16 rows x 128 cols ------------
// 8 warps x 16 prod rows (r = c*32+m; warp w: class w>>1, m-half w&1).
// Per kc: ONE A row-pair (12-instr build) reused across 16 n-tiles -> halves
// non-MMA issue pressure vs the 32x64 tile. Each warp owns its rows' full
// n-range: epilogue is shfl + direct store (no cross-warp smem reduce).
__global__ __launch_bounds__(256, 2)
void attn_mma(const float* __restrict__ men, const float* __restrict__ vis,
              const unsigned* __restrict__ awp,
              const float* __restrict__ ab1, const float* __restrict__ aw2,
              const float* __restrict__ ab2,
              const float* __restrict__ mm, const float* __restrict__ cm,
              float* __restrict__ out)
{
    __shared__ __align__(16) float    men_s[2][32][36];
    __shared__ __align__(16) float    vis_s[2][4][36];
    __shared__ __align__(16) unsigned b_pk[2][4608];   // 8 chunks x 576 words

    const int tid = threadIdx.x;
    const int lane = tid & 31, wid = tid >> 5;
    const int c_loc = wid >> 1;          // class within tile (0..3)
    const int mbase = (wid & 1) * 16;    // m-half within class
    const int c0 = blockIdx.x * 4;
    const int m0 = blockIdx.y * 32;
    const int b  = blockIdx.z;

    const float* menB = men + (size_t)(b * 64 + m0) * 512;
    const float* visB = vis + (size_t)(b * 36 + c0) * 512;

    const int laneoff = lane * 16 + (lane >> 1) * 4;   // skewed frag base
    const int mr = lane >> 2, kq = lane & 3;

    float acc[16][4];
    float attn_acc[2] = {0.f, 0.f};

    auto issue = [&](int s) {
        const int buf = s & 1;
        const int koff = (s & 15) * 32;
        {   // men: 32 rows x 32 k
            int r = tid >> 3, k4 = tid & 7;
            cp16(&men_s[buf][r][k4 * 4], menB + (size_t)r * 512 + koff + k4 * 4);
        }
        if (tid < 32) {  // vis: 4 x 32
            int c = tid >> 3, k4 = tid & 7;
            cp16(&vis_s[buf][c][k4 * 4], visB + (size_t)c * 512 + koff + k4 * 4);
        }
        const unsigned* src = awp + (size_t)s * 4608 + tid * 4;
        unsigned* dstb = &b_pk[buf][tid * 4];
#pragma unroll
        for (int p = 0; p < 4; p++)
            cp16(dstb + p * 1024, src + p * 1024);
        if (tid < 128) cp16(dstb + 4096, src + 4096);
    };

    issue(0);
    CP_COMMIT();

    for (int s = 0; s < 64; s++) {
        if (s + 1 < 64) { issue(s + 1); CP_COMMIT(); CP_WAIT1(); }
        else            { CP_WAIT0(); }
        __syncthreads();

        const int buf = s & 1;
        const int ks = s & 15, ni = s >> 4;

        if (ks == 0) {
#pragma unroll
            for (int t = 0; t < 16; t++)
#pragma unroll
                for (int j = 0; j < 4; j++) acc[t][j] = 0.f;
        }

#pragma unroll
        for (int kc = 0; kc < 4; kc++) {
            const int kA = kc * 8 + kq;
            float v0 = vis_s[buf][c_loc][kA];
            float v1 = vis_s[buf][c_loc][kA + 4];
            float m00 = men_s[buf][mbase + mr][kA];
            float m01 = men_s[buf][mbase + mr][kA + 4];
            float m10 = men_s[buf][mbase + mr + 8][kA];
            float m11 = men_s[buf][mbase + mr + 8][kA + 4];
            unsigned a0 = f2tf32(m00 * v0), a1 = f2tf32(m10 * v0);
            unsigned a2 = f2tf32(m01 * v1), a3 = f2tf32(m11 * v1);

#pragma unroll
            for (int h = 0; h < 2; h++) {
                const unsigned* cb = &b_pk[buf][(kc * 2 + h) * 576 + laneoff];
                uint4 q0 = *(const uint4*)(cb);
                uint4 q1 = *(const uint4*)(cb + 4);
                uint4 q2 = *(const uint4*)(cb + 8);
                uint4 q3 = *(const uint4*)(cb + 12);
                float (*ah)[4] = acc + h * 8;
                mma_tf32(ah[0], a0, a1, a2, a3, q0.x, q0.y);
                mma_tf32(ah[1], a0, a1, a2, a3, q0.z, q0.w);
                mma_tf32(ah[2], a0, a1, a2, a3, q1.x, q1.y);
                mma_tf32(ah[3], a0, a1, a2, a3, q1.z, q1.w);
                mma_tf32(ah[4], a0, a1, a2, a3, q2.x, q2.y);
                mma_tf32(ah[5], a0, a1, a2, a3, q2.z, q2.w);
                mma_tf32(ah[6], a0, a1, a2, a3, q3.x, q3.y);
                mma_tf32(ah[7], a0, a1, a2, a3, q3.z, q3.w);
            }
        }

        if (ks == 15) {
            // fold N-range [ni*128, ni*128+128): attn += relu(acc+ab1)*aw2
#pragma unroll
            for (int t = 0; t < 16; t++) {
                int n = ni * 128 + (t >> 3) * 64 + (t & 7) * 8 + 2 * (lane & 3);
                float bb0 = __ldg(&ab1[n]),  bb1 = __ldg(&ab1[n + 1]);
                float w0  = __ldg(&aw2[n]),  w1  = __ldg(&aw2[n + 1]);
                attn_acc[0] += fmaxf(acc[t][0] + bb0, 0.f) * w0
                             + fmaxf(acc[t][1] + bb1, 0.f) * w1;
                attn_acc[1] += fmaxf(acc[t][2] + bb0, 0.f) * w0
                             + fmaxf(acc[t][3] + bb1, 0.f) * w1;
            }
        }
        __syncthreads();
    }

    // reduce over the 4 col-pair lanes; each warp owns rows exclusively
    const float bias2 = ab2[0];
#pragma unroll
    for (int i = 0; i < 2; i++) {
        float v = attn_acc[i];
        v += __shfl_xor_sync(0xffffffffu, v, 1);
        v += __shfl_xor_sync(0xffffffffu, v, 2);
        if ((lane & 3) == 0) {
            int m = m0 + mbase + mr + i * 8;
            int c = c0 + c_loc;
            float val = v + bias2;
            val *= mm[b * 64 + m] * cm[b * 36 + c];
            out[(size_t)(b * 64 + m) * 36 + c] = (val != 0.f) ? val : NEG_INF_F;
        }
    }
}

// ---------------- launch ---------------------------------------------------
extern "C" void kernel_launch(void* const* d_in, const int* in_sizes, int n_in,
                              void* d_out, int out_size)
{
    const float* me  = (const float*)d_in[0];
    const float* cl  = (const float*)d_in[1];
    const float* mm  = (const float*)d_in[2];
    const float* cm  = (const float*)d_in[3];
    const float* vw1 = (const float*)d_in[4];
    const float* vb1 = (const float*)d_in[5];
    const float* vw2 = (const float*)d_in[6];
    const float* vb2 = (const float*)d_in[7];
    const float* mw1 = (const float*)d_in[8];
    const float* mb1 = (const float*)d_in[9];
    const float* mw2 = (const float*)d_in[10];
    const float* mb2 = (const float*)d_in[11];
    const float* aw1 = (const float*)d_in[12];
    const float* ab1 = (const float*)d_in[13];
    const float* aw2 = (const float*)d_in[14];
    const float* ab2 = (const float*)d_in[15];
    float* out = (float*)d_out;

    void *p;
    cudaGetSymbolAddress(&p, g_men_h);  float*    men_h = (float*)p;
    cudaGetSymbolAddress(&p, g_men);    float*    menp  = (float*)p;
    cudaGetSymbolAddress(&p, g_vis_h);  float*    vis_h = (float*)p;
    cudaGetSymbolAddress(&p, g_vis);    float*    visp  = (float*)p;
    cudaGetSymbolAddress(&p, g_cl_pad); float*    clp   = (float*)p;
    cudaGetSymbolAddress(&p, g_mw1t);   unsigned* mw1t  = (unsigned*)p;
    cudaGetSymbolAddress(&p, g_mw2t);   unsigned* mw2t  = (unsigned*)p;
    cudaGetSymbolAddress(&p, g_vw1t);   unsigned* vw1t  = (unsigned*)p;
    cudaGetSymbolAddress(&p, g_vw2t);   unsigned* vw2t  = (unsigned*)p;
    cudaGetSymbolAddress(&p, g_aw1p);   unsigned* awp   = (unsigned*)p;

    // #0: all prep
    prep_all<<<4736, 256>>>(cl, clp, mw1, mw1t, mw2, mw2t,
                            vw1, vw1t, vw2, vw2t, aw1, awp);

    // #1/#2: both MLP layers merged (400 blocks each)
    gemm_mma2<true ><<<dim3(8, 50), 256>>>(me,    mw1t, mb1, men_h,
                                           clp,   vw1t, vb1, vis_h, 1024, 32);
    gemm_mma2<false><<<dim3(8, 50), 256>>>(men_h, mw2t, mb2, menp,
                                           vis_h, vw2t, vb2, visp,  512, 32);

    // #3: fused attention (16x128 warp tile)
    attn_mma<<<dim3(9, 2, 32), 256>>>(menp, visp, awp, ab1, aw2, ab2,
                                      mm, cm, out);
}